// round 1
// baseline (speedup 1.0000x reference)
#include <cuda_runtime.h>

// Problem constants
constexpr int BATCH = 4;
constexpr int T     = 2048;
constexpr int NH    = 16;
constexpr int DH    = 64;
constexpr int DM    = 1024;      // NH*DH
constexpr int MROWS = BATCH * T; // 8192

// Scratch (device globals; no allocation allowed)
__device__ float g_qkv[(size_t)MROWS * 3 * DM]; // [B*T, 3*DM] : [.., 3, H, Dh]
__device__ float g_kt [(size_t)BATCH * NH * DH * T]; // K transposed: [b,h,d,t]
__device__ float g_ctx[(size_t)MROWS * DM];     // context [B*T, DM]

__device__ __forceinline__ float ninf() { return __int_as_float(0xff800000u); }

// ---------------------------------------------------------------------------
// Tiled SGEMM: C[M,N] = A[M,K] @ Bm[K,N] + bias[N]. M%128==0, N%128==0, K%8==0.
// 256 threads, BM=BN=128, BK=8, 8x8 per-thread tile.
// ---------------------------------------------------------------------------
__global__ __launch_bounds__(256) void sgemm_bias_kernel(
    const float* __restrict__ A, const float* __restrict__ Bm,
    const float* __restrict__ bias, float* __restrict__ C,
    int M, int N, int K)
{
    __shared__ float As[8][128];
    __shared__ float Bs[8][128];
    const int tid = threadIdx.x;
    const int tc = tid % 16;     // 0..15 -> 8 cols each
    const int tr = tid / 16;     // 0..15 -> 8 rows each
    const int row0 = blockIdx.y * 128;
    const int col0 = blockIdx.x * 128;

    float acc[8][8];
#pragma unroll
    for (int i = 0; i < 8; i++)
#pragma unroll
        for (int j = 0; j < 8; j++) acc[i][j] = 0.f;

    for (int k0 = 0; k0 < K; k0 += 8) {
#pragma unroll
        for (int i = 0; i < 4; i++) {
            int idx = tid + i * 256;           // 0..1023
            int m  = idx >> 3, kk  = idx & 7;  // A tile 128x8
            As[kk][m] = A[(size_t)(row0 + m) * K + (k0 + kk)];
            int kk2 = idx >> 7, n = idx & 127; // B tile 8x128
            Bs[kk2][n] = Bm[(size_t)(k0 + kk2) * N + (col0 + n)];
        }
        __syncthreads();
#pragma unroll
        for (int kk = 0; kk < 8; kk++) {
            float ra[8], rb[8];
#pragma unroll
            for (int i = 0; i < 8; i++) ra[i] = As[kk][tr * 8 + i];
#pragma unroll
            for (int j = 0; j < 8; j++) rb[j] = Bs[kk][tc * 8 + j];
#pragma unroll
            for (int i = 0; i < 8; i++)
#pragma unroll
                for (int j = 0; j < 8; j++) acc[i][j] += ra[i] * rb[j];
        }
        __syncthreads();
    }

#pragma unroll
    for (int i = 0; i < 8; i++) {
        int m = row0 + tr * 8 + i;
#pragma unroll
        for (int j = 0; j < 8; j++) {
            int n = col0 + tc * 8 + j;
            C[(size_t)m * N + n] = acc[i][j] + bias[n];
        }
    }
}

// ---------------------------------------------------------------------------
// Transpose K out of the packed qkv buffer into [b,h,d,t] (coalesced writes).
// ---------------------------------------------------------------------------
__global__ void transpose_k_kernel()
{
    size_t i = (size_t)blockIdx.x * blockDim.x + threadIdx.x;
    const size_t total = (size_t)BATCH * NH * DH * T;
    if (i >= total) return;
    int k = (int)(i % T);
    size_t r = i / T;
    int d = (int)(r % DH); r /= DH;
    int h = (int)(r % NH);
    int b = (int)(r / NH);
    g_kt[i] = g_qkv[((size_t)(b * T + k)) * (3 * DM) + DM + h * DH + d];
}

// ---------------------------------------------------------------------------
// Attention: one CTA per (b, h, 16-query tile). 256 threads.
// Pass 1: streaming online max/sum. Pass 2: recompute scores, write weights,
// accumulate context via smem probability tile.
// ---------------------------------------------------------------------------
__global__ __launch_bounds__(256) void attn_kernel(float* __restrict__ weights)
{
    constexpr int QT = 16;
    const int q0 = blockIdx.x * QT;
    const int h  = blockIdx.y;
    const int b  = blockIdx.z;
    const int tid = threadIdx.x;
    const int lane = tid & 31, warp = tid >> 5;

    __shared__ float qs[QT][DH];       // 4 KB
    __shared__ float p[QT][257];       // 16.4 KB probability tile (padded)
    __shared__ float redm[QT][8], reds[QT][8];
    __shared__ float mfin[QT], sinv[QT];

    // Load Q tile
    for (int i = tid; i < QT * DH; i += 256) {
        int qq = i / DH, d = i % DH;
        qs[qq][d] = g_qkv[((size_t)(b * T + q0 + qq)) * (3 * DM) + h * DH + d];
    }
    __syncthreads();

    const float* ktb = g_kt + ((size_t)(b * NH + h)) * DH * T;
    const int klim = q0 + QT;             // exclusive max k needed
    const int nch = (klim + 255) / 256;   // 256-wide k chunks

    // ---- Pass 1: thread-local online (max, sum) ----
    float m[QT], s[QT];
#pragma unroll
    for (int q = 0; q < QT; q++) { m[q] = ninf(); s[q] = 0.f; }

    for (int c = 0; c < nch; c++) {
        const int k = c * 256 + tid;
        float acc[QT];
#pragma unroll
        for (int q = 0; q < QT; q++) acc[q] = 0.f;
#pragma unroll 4
        for (int d = 0; d < DH; d++) {
            float kv = ktb[(size_t)d * T + k];
#pragma unroll
            for (int q = 0; q < QT; q++) acc[q] += kv * qs[q][d];
        }
#pragma unroll
        for (int q = 0; q < QT; q++) {
            int qi = q0 + q;
            float x = (k <= qi) ? acc[q] * 0.125f : ninf();
            if (x > m[q]) { s[q] = s[q] * __expf(m[q] - x) + 1.0f; m[q] = x; }
            else if (x != ninf()) s[q] += __expf(x - m[q]);
        }
    }

    // ---- Reduce (max,sum) across the block (inf-safe merges) ----
#pragma unroll
    for (int q = 0; q < QT; q++) {
        float mm = m[q], ss = s[q];
        for (int off = 16; off; off >>= 1) {
            float mo = __shfl_xor_sync(0xffffffffu, mm, off);
            float so = __shfl_xor_sync(0xffffffffu, ss, off);
            float mn = fmaxf(mm, mo);
            float e1 = (mm == ninf()) ? 0.f : __expf(mm - mn);
            float e2 = (mo == ninf()) ? 0.f : __expf(mo - mn);
            ss = ss * e1 + so * e2;
            mm = mn;
        }
        if (lane == 0) { redm[q][warp] = mm; reds[q][warp] = ss; }
    }
    __syncthreads();
    if (tid < QT) {
        float mm = ninf(), ss = 0.f;
#pragma unroll
        for (int w = 0; w < 8; w++) {
            float mo = redm[tid][w], so = reds[tid][w];
            float mn = fmaxf(mm, mo);
            float e1 = (mm == ninf()) ? 0.f : __expf(mm - mn);
            float e2 = (mo == ninf()) ? 0.f : __expf(mo - mn);
            ss = ss * e1 + so * e2;
            mm = mn;
        }
        mfin[tid] = mm;
        sinv[tid] = 1.0f / ss;   // every row has at least k==q unmasked
    }
    __syncthreads();

    // ---- Pass 2: weights + context ----
    const int dd = tid & 63;     // head dim handled by this thread
    const int qg = tid >> 6;     // q-group 0..3 -> rows {qg, qg+4, qg+8, qg+12}
    float ctx[4] = {0.f, 0.f, 0.f, 0.f};
    const float* vbase = g_qkv + (size_t)b * T * (3 * DM) + 2 * DM + h * DH;
    float* wbase = weights + ((size_t)((b * NH + h) * T) + q0) * T;

    for (int c = 0; c < nch; c++) {
        const int k = c * 256 + tid;
        float acc[QT];
#pragma unroll
        for (int q = 0; q < QT; q++) acc[q] = 0.f;
#pragma unroll 4
        for (int d = 0; d < DH; d++) {
            float kv = ktb[(size_t)d * T + k];
#pragma unroll
            for (int q = 0; q < QT; q++) acc[q] += kv * qs[q][d];
        }
#pragma unroll
        for (int q = 0; q < QT; q++) {
            int qi = q0 + q;
            float x = (k <= qi) ? acc[q] * 0.125f : ninf();
            float e = __expf(x - mfin[q]) * sinv[q];   // 0 when masked
            p[q][tid] = e;
            wbase[(size_t)q * T + k] = e;
        }
        __syncthreads();

        const int kcnt = min(256, klim - c * 256);
        for (int kl = 0; kl < kcnt; kl++) {
            float v = vbase[(size_t)(c * 256 + kl) * (3 * DM) + dd];
#pragma unroll
            for (int qq = 0; qq < 4; qq++)
                ctx[qq] += p[qg + qq * 4][kl] * v;
        }
        __syncthreads();
    }

    // Zero-fill the untouched (strictly future) weight columns
    for (int k = nch * 256 + tid; k < T; k += 256) {
#pragma unroll
        for (int q = 0; q < QT; q++) wbase[(size_t)q * T + k] = 0.f;
    }

    // Write context
#pragma unroll
    for (int qq = 0; qq < 4; qq++) {
        int qi = q0 + qg + qq * 4;
        g_ctx[((size_t)(b * T + qi)) * DM + h * DH + dd] = ctx[qq];
    }
}

// ---------------------------------------------------------------------------
extern "C" void kernel_launch(void* const* d_in, const int* in_sizes, int n_in,
                              void* d_out, int out_size)
{
    const float* x     = (const float*)d_in[0];
    const float* w_qkv = (const float*)d_in[1];
    const float* b_qkv = (const float*)d_in[2];
    const float* w_out = (const float*)d_in[3];
    const float* b_out = (const float*)d_in[4];

    float* out     = (float*)d_out;                       // [B,T,DM]
    float* weights = out + (size_t)MROWS * DM;            // [B,H,T,T]

    float *qkv_p, *kt_p, *ctx_p;
    cudaGetSymbolAddress((void**)&qkv_p, g_qkv);
    cudaGetSymbolAddress((void**)&kt_p,  g_kt);
    cudaGetSymbolAddress((void**)&ctx_p, g_ctx);
    (void)kt_p;

    // 1) QKV projection: [8192,1024] @ [1024,3072] + b_qkv
    dim3 g1((3 * DM) / 128, MROWS / 128);
    sgemm_bias_kernel<<<g1, 256>>>(x, w_qkv, b_qkv, qkv_p, MROWS, 3 * DM, DM);

    // 2) Transpose K to [b,h,d,t]
    const size_t tot = (size_t)BATCH * NH * DH * T;
    transpose_k_kernel<<<(int)((tot + 255) / 256), 256>>>();

    // 3) Attention (weights written directly to d_out tail, context to scratch)
    dim3 g2(T / 16, NH, BATCH);
    attn_kernel<<<g2, 256>>>(weights);

    // 4) Output projection: [8192,1024] @ [1024,1024] + b_out
    dim3 g3(DM / 128, MROWS / 128);
    sgemm_bias_kernel<<<g3, 256>>>(ctx_p, w_out, b_out, out, MROWS, DM, DM);
}

// round 2
// speedup vs baseline: 1.7173x; 1.7173x over previous
#include <cuda_runtime.h>

// Problem constants
constexpr int BATCH = 4;
constexpr int T     = 2048;
constexpr int NH    = 16;
constexpr int DH    = 64;
constexpr int DM    = 1024;      // NH*DH
constexpr int MROWS = BATCH * T; // 8192

// Scratch (device globals; no allocation allowed)
__device__ float g_qkv[(size_t)MROWS * 3 * DM]; // [B*T, 3*DM]
__device__ float g_ctx[(size_t)MROWS * DM];     // context [B*T, DM]
__device__ float g_m [(size_t)BATCH * NH * T];  // row max
__device__ float g_si[(size_t)BATCH * NH * T];  // row 1/sumexp

__device__ __forceinline__ float ninf() { return __int_as_float(0xff800000u); }

// ---------------------------------------------------------------------------
// SGEMM: C[M,N] = A[M,K] @ B[K,N] + bias. BM=BN=128, BK=16, 256 thr, 8x8 tile.
// ---------------------------------------------------------------------------
__global__ __launch_bounds__(256) void sgemm_bias_kernel(
    const float* __restrict__ A, const float* __restrict__ Bm,
    const float* __restrict__ bias, float* __restrict__ C,
    int M, int N, int K)
{
    __shared__ float As[16][128];
    __shared__ float Bs[16][128];
    const int tid = threadIdx.x;
    const int tc = tid % 16;
    const int tr = tid / 16;
    const int row0 = blockIdx.y * 128;
    const int col0 = blockIdx.x * 128;

    float acc[8][8];
#pragma unroll
    for (int i = 0; i < 8; i++)
#pragma unroll
        for (int j = 0; j < 8; j++) acc[i][j] = 0.f;

    const int ar = tid >> 1;           // A row within tile (0..127)
    const int as = tid & 1;            // A f4 slot parity
    const int br = tid >> 4;           // B row within tile (0..15)
    const int bs = tid & 15;           // B f4 slot

    for (int k0 = 0; k0 < K; k0 += 16) {
        // A tile 128x16 -> As[k][m] (transposed)
#pragma unroll
        for (int j = 0; j < 2; j++) {
            int slot = as + j * 2;     // 0..3
            float4 v = *(const float4*)&A[(size_t)(row0 + ar) * K + k0 + slot * 4];
            As[slot * 4 + 0][ar] = v.x;
            As[slot * 4 + 1][ar] = v.y;
            As[slot * 4 + 2][ar] = v.z;
            As[slot * 4 + 3][ar] = v.w;
        }
        // B tile 16x128 -> Bs[k][n]
#pragma unroll
        for (int j = 0; j < 2; j++) {
            int slot = bs + j * 16;    // 0..31
            *(float4*)&Bs[br][slot * 4] =
                *(const float4*)&Bm[(size_t)(k0 + br) * N + col0 + slot * 4];
        }
        __syncthreads();
#pragma unroll
        for (int kk = 0; kk < 16; kk++) {
            float4 a0 = *(float4*)&As[kk][tr * 8];
            float4 a1 = *(float4*)&As[kk][tr * 8 + 4];
            float4 b0 = *(float4*)&Bs[kk][tc * 8];
            float4 b1 = *(float4*)&Bs[kk][tc * 8 + 4];
            float ra[8] = {a0.x,a0.y,a0.z,a0.w,a1.x,a1.y,a1.z,a1.w};
            float rb[8] = {b0.x,b0.y,b0.z,b0.w,b1.x,b1.y,b1.z,b1.w};
#pragma unroll
            for (int i = 0; i < 8; i++)
#pragma unroll
                for (int j = 0; j < 8; j++) acc[i][j] += ra[i] * rb[j];
        }
        __syncthreads();
    }

#pragma unroll
    for (int i = 0; i < 8; i++) {
        int m = row0 + tr * 8 + i;
#pragma unroll
        for (int j = 0; j < 8; j++) {
            int n = col0 + tc * 8 + j;
            C[(size_t)m * N + n] = acc[i][j] + bias[n];
        }
    }
}

// ---------------------------------------------------------------------------
// K2: raw scores S = Q@K^T / 8 into weights buffer. Tile 64q x 128k x 64d.
// Upper-triangle tiles are zero-filled. grid (T/128, T/64, B*NH), 256 thr.
// ---------------------------------------------------------------------------
__global__ __launch_bounds__(256) void score_kernel(float* __restrict__ weights)
{
    const int k0 = blockIdx.x * 128;
    const int q0 = blockIdx.y * 64;
    const int bh = blockIdx.z;
    const int b = bh >> 4, h = bh & 15;
    const int tid = threadIdx.x;

    float* wbase = weights + ((size_t)bh * T + q0) * T + k0;

    if (k0 >= q0 + 64) {
        // pure future tile: zero fill (64x128 floats)
        const int r = tid >> 2;           // q row 0..63
        const int s0 = tid & 3;
        float4 z = make_float4(0.f, 0.f, 0.f, 0.f);
#pragma unroll
        for (int j = 0; j < 8; j++) {
            int slot = s0 + j * 4;        // 0..31
            *(float4*)&wbase[(size_t)r * T + slot * 4] = z;
        }
        return;
    }

    __shared__ float Qs[64][64];   // [d][q]
    __shared__ float Ks[64][128];  // [d][k]

    const float* qkv = g_qkv;
    // load Q tile 64q x 64d, transpose into Qs[d][q]
    {
        int r = tid >> 2;              // q 0..63
        int s0 = tid & 3;
#pragma unroll
        for (int j = 0; j < 4; j++) {
            int slot = s0 + j * 4;     // f4 slot 0..15
            float4 v = *(const float4*)&qkv[((size_t)(b * T + q0 + r)) * (3 * DM) + h * DH + slot * 4];
            Qs[slot * 4 + 0][r] = v.x;
            Qs[slot * 4 + 1][r] = v.y;
            Qs[slot * 4 + 2][r] = v.z;
            Qs[slot * 4 + 3][r] = v.w;
        }
    }
    // load K tile 128k x 64d, transpose into Ks[d][k]
    {
        int r = tid >> 1;              // k 0..127
        int s0 = tid & 1;
#pragma unroll
        for (int j = 0; j < 8; j++) {
            int slot = s0 + j * 2;     // 0..15
            float4 v = *(const float4*)&qkv[((size_t)(b * T + k0 + r)) * (3 * DM) + DM + h * DH + slot * 4];
            Ks[slot * 4 + 0][r] = v.x;
            Ks[slot * 4 + 1][r] = v.y;
            Ks[slot * 4 + 2][r] = v.z;
            Ks[slot * 4 + 3][r] = v.w;
        }
    }
    __syncthreads();

    const int tq = tid >> 4;           // 0..15 -> 4 q rows
    const int tk = tid & 15;           // 0..15 -> 8 k cols
    float acc[4][8];
#pragma unroll
    for (int i = 0; i < 4; i++)
#pragma unroll
        for (int j = 0; j < 8; j++) acc[i][j] = 0.f;

#pragma unroll 8
    for (int d = 0; d < 64; d++) {
        float4 a = *(float4*)&Qs[d][tq * 4];
        float4 b0 = *(float4*)&Ks[d][tk * 8];
        float4 b1 = *(float4*)&Ks[d][tk * 8 + 4];
        float ra[4] = {a.x, a.y, a.z, a.w};
        float rb[8] = {b0.x,b0.y,b0.z,b0.w,b1.x,b1.y,b1.z,b1.w};
#pragma unroll
        for (int i = 0; i < 4; i++)
#pragma unroll
            for (int j = 0; j < 8; j++) acc[i][j] += ra[i] * rb[j];
    }

    // write scaled + masked
#pragma unroll
    for (int i = 0; i < 4; i++) {
        int qg = q0 + tq * 4 + i;
        float out[8];
#pragma unroll
        for (int j = 0; j < 8; j++) {
            int kg = k0 + tk * 8 + j;
            out[j] = (kg <= qg) ? acc[i][j] * 0.125f : 0.f;
        }
        *(float4*)&wbase[(size_t)(tq * 4 + i) * T + tk * 8]     = make_float4(out[0],out[1],out[2],out[3]);
        *(float4*)&wbase[(size_t)(tq * 4 + i) * T + tk * 8 + 4] = make_float4(out[4],out[5],out[6],out[7]);
    }
}

// ---------------------------------------------------------------------------
// K3: per-row softmax stats from stored raw scores. One warp per row.
// ---------------------------------------------------------------------------
__global__ __launch_bounds__(256) void stats_kernel(const float* __restrict__ weights)
{
    const int row = blockIdx.x * 8 + (threadIdx.x >> 5);  // global (b*h*T + q)
    const int lane = threadIdx.x & 31;
    const int q = row & (T - 1);
    const float* wrow = weights + (size_t)row * T;

    float m = ninf(), s = 0.f;
    for (int k = lane; k <= q; k += 32) {
        float x = wrow[k];
        if (x > m) { s = s * __expf(m - x) + 1.0f; m = x; }
        else s += __expf(x - m);
    }
#pragma unroll
    for (int off = 16; off; off >>= 1) {
        float mo = __shfl_xor_sync(0xffffffffu, m, off);
        float so = __shfl_xor_sync(0xffffffffu, s, off);
        float mn = fmaxf(m, mo);
        float e1 = (m == ninf()) ? 0.f : __expf(m - mn);
        float e2 = (mo == ninf()) ? 0.f : __expf(mo - mn);
        s = s * e1 + so * e2;
        m = mn;
    }
    if (lane == 0) {
        g_m[row] = m;
        g_si[row] = 1.0f / s;
    }
}

// ---------------------------------------------------------------------------
// K4: probabilities + context. CTA per (b,h,64-q tile). K chunks of 64.
// Reads raw scores, writes normalized weights, accumulates ctx = P @ V.
// ---------------------------------------------------------------------------
__global__ __launch_bounds__(256) void pv_kernel(float* __restrict__ weights)
{
    const int q0 = blockIdx.x * 64;
    const int h  = blockIdx.y;
    const int b  = blockIdx.z;
    const int bh = b * NH + h;
    const int tid = threadIdx.x;

    __shared__ float Ps[64][68];   // [k][q] probabilities
    __shared__ float Vs[64][68];   // [k][d]
    __shared__ float sm_m[64], sm_si[64];

    if (tid < 64) {
        sm_m[tid]  = g_m [(size_t)bh * T + q0 + tid];
        sm_si[tid] = g_si[(size_t)bh * T + q0 + tid];
    }
    __syncthreads();

    const int tq = tid >> 4;       // 0..15 -> 4 q rows
    const int td = tid & 15;       // 0..15 -> 4 d cols
    float acc[4][4];
#pragma unroll
    for (int i = 0; i < 4; i++)
#pragma unroll
        for (int j = 0; j < 4; j++) acc[i][j] = 0.f;

    float* wbase = weights + ((size_t)bh * T + q0) * T;
    const float* vbase = g_qkv + (size_t)b * T * (3 * DM) + 2 * DM + h * DH;

    const int nch = blockIdx.x + 1;   // chunks of 64 keys covering k <= q0+63

    const int sr = tid >> 2;          // 0..63 (S-tile q row / V k row)
    const int ss = tid & 3;

    for (int c = 0; c < nch; c++) {
        const int k0 = c * 64;
        // Load S tile 64x64, convert to p, write back, stash transposed in Ps
        {
            float m = sm_m[sr], si = sm_si[sr];
            int qg = q0 + sr;
#pragma unroll
            for (int j = 0; j < 4; j++) {
                int slot = ss + j * 4;             // 0..15
                int kt = slot * 4;
                float4 v = *(float4*)&wbase[(size_t)sr * T + k0 + kt];
                float p0 = (k0 + kt + 0 <= qg) ? __expf(v.x - m) * si : 0.f;
                float p1 = (k0 + kt + 1 <= qg) ? __expf(v.y - m) * si : 0.f;
                float p2 = (k0 + kt + 2 <= qg) ? __expf(v.z - m) * si : 0.f;
                float p3 = (k0 + kt + 3 <= qg) ? __expf(v.w - m) * si : 0.f;
                *(float4*)&wbase[(size_t)sr * T + k0 + kt] = make_float4(p0,p1,p2,p3);
                Ps[kt + 0][sr] = p0;
                Ps[kt + 1][sr] = p1;
                Ps[kt + 2][sr] = p2;
                Ps[kt + 3][sr] = p3;
            }
        }
        // Load V chunk 64k x 64d
        {
#pragma unroll
            for (int j = 0; j < 4; j++) {
                int slot = ss + j * 4;
                *(float4*)&Vs[sr][slot * 4] =
                    *(const float4*)&vbase[(size_t)(k0 + sr) * (3 * DM) + slot * 4];
            }
        }
        __syncthreads();

#pragma unroll 4
        for (int k = 0; k < 64; k++) {
            float4 a = *(float4*)&Ps[k][tq * 4];
            float4 v = *(float4*)&Vs[k][td * 4];
            float ra[4] = {a.x, a.y, a.z, a.w};
            float rb[4] = {v.x, v.y, v.z, v.w};
#pragma unroll
            for (int i = 0; i < 4; i++)
#pragma unroll
                for (int j = 0; j < 4; j++) acc[i][j] += ra[i] * rb[j];
        }
        __syncthreads();
    }

#pragma unroll
    for (int i = 0; i < 4; i++) {
        int qg = q0 + tq * 4 + i;
        *(float4*)&g_ctx[((size_t)(b * T + qg)) * DM + h * DH + td * 4] =
            make_float4(acc[i][0], acc[i][1], acc[i][2], acc[i][3]);
    }
}

// ---------------------------------------------------------------------------
extern "C" void kernel_launch(void* const* d_in, const int* in_sizes, int n_in,
                              void* d_out, int out_size)
{
    const float* x     = (const float*)d_in[0];
    const float* w_qkv = (const float*)d_in[1];
    const float* b_qkv = (const float*)d_in[2];
    const float* w_out = (const float*)d_in[3];
    const float* b_out = (const float*)d_in[4];

    float* out     = (float*)d_out;                       // [B,T,DM]
    float* weights = out + (size_t)MROWS * DM;            // [B,H,T,T]

    float *qkv_p, *ctx_p;
    cudaGetSymbolAddress((void**)&qkv_p, g_qkv);
    cudaGetSymbolAddress((void**)&ctx_p, g_ctx);

    // 1) QKV projection
    dim3 g1((3 * DM) / 128, MROWS / 128);
    sgemm_bias_kernel<<<g1, 256>>>(x, w_qkv, b_qkv, qkv_p, MROWS, 3 * DM, DM);

    // 2) Raw scores -> weights buffer (zeros above the diagonal)
    dim3 g2(T / 128, T / 64, BATCH * NH);
    score_kernel<<<g2, 256>>>(weights);

    // 3) Row softmax stats
    stats_kernel<<<BATCH * NH * T / 8, 256>>>(weights);

    // 4) Probabilities (in-place in weights) + context = P@V
    dim3 g4(T / 64, NH, BATCH);
    pv_kernel<<<g4, 256>>>(weights);

    // 5) Output projection
    dim3 g5(DM / 128, MROWS / 128);
    sgemm_bias_kernel<<<g5, 256>>>(ctx_p, w_out, b_out, out, MROWS, DM, DM);
}